// round 1
// baseline (speedup 1.0000x reference)
#include <cuda_runtime.h>
#include <math.h>

#define BNUM 4096
#define EDIM 128
#define LHID 128
#define HDIM 64
#define NGATE 512
#define NAB 300
#define NMV 900
#define INDIM 7808

// ---------------- scratch (device globals; no allocation allowed) -------------
__device__ float g_Tab[12 * NAB * NGATE];     // 7.37 MB
__device__ float g_Tmv[48 * NMV * NGATE];     // 88.5 MB
__device__ float g_WcombT[84 * NGATE];
__device__ float g_WhhT[LHID * NGATE];
__device__ float g_bias[NGATE];
__device__ float g_h1[BNUM * LHID];
__device__ float g_c1[BNUM * LHID];

typedef unsigned long long u64;

__device__ __forceinline__ u64 pk2(float x, float y) {
    u64 r;
    asm("mov.b64 %0, {%1, %2};" : "=l"(r) : "r"(__float_as_uint(x)), "r"(__float_as_uint(y)));
    return r;
}
__device__ __forceinline__ void upk2(u64 v, float& x, float& y) {
    unsigned a, b;
    asm("mov.b64 {%0, %1}, %2;" : "=r"(a), "=r"(b) : "l"(v));
    x = __uint_as_float(a); y = __uint_as_float(b);
}
__device__ __forceinline__ void ffma2(u64& d, u64 a, u64 b) {
    asm("fma.rn.f32x2 %0, %1, %2, %0;" : "+l"(d) : "l"(a), "l"(b));
}
__device__ __forceinline__ void fadd2(u64& d, u64 a) {
    asm("add.rn.f32x2 %0, %1, %0;" : "+l"(d) : "l"(a));
}

// ---------------- Stage A: per-slot tables  T[s][v][j] = sum_k emb[v][k]*Wih[j][base+k]
#define SBPAD 68
__global__ __launch_bounds__(256) void kernelA(
    const float* __restrict__ emb, int V,
    const float* __restrict__ Wih, int colBase0,
    float* __restrict__ out)
{
    extern __shared__ float sm[];
    float2* As = (float2*)sm;                 // [64*128] duplicated-pair A
    float*  Bs = sm + 64 * 128 * 2;           // [128][SBPAD]
    const int tid = threadIdx.x;
    const int v0 = blockIdx.x * 64, j0 = blockIdx.y * 64;
    const int colBase = colBase0 + blockIdx.z * EDIM;
    float* outP = out + (size_t)blockIdx.z * V * NGATE;

    for (int idx = tid; idx < 64 * 128; idx += 256) {
        int m = idx >> 7, k = idx & 127;
        int v = v0 + m;
        float a = (v < V) ? emb[v * EDIM + k] : 0.f;
        As[m * 128 + k] = make_float2(a, a);
    }
    for (int idx = tid; idx < 64 * 128; idx += 256) {
        int n = idx >> 7, k = idx & 127;
        Bs[k * SBPAD + n] = Wih[(size_t)(j0 + n) * INDIM + colBase + k];
    }
    __syncthreads();

    const int tn = tid & 15, tm = tid >> 4;
    const int m0 = tm * 4, n0 = tn * 4;
    u64 acc[4][2];
#pragma unroll
    for (int i = 0; i < 4; i++) { acc[i][0] = 0ULL; acc[i][1] = 0ULL; }

#pragma unroll 4
    for (int k = 0; k < 128; k++) {
        float4 b4 = *(const float4*)&Bs[k * SBPAD + n0];
        u64 b01 = pk2(b4.x, b4.y), b23 = pk2(b4.z, b4.w);
#pragma unroll
        for (int i = 0; i < 4; i++) {
            u64 aa = *(const u64*)&As[(m0 + i) * 128 + k];
            ffma2(acc[i][0], aa, b01);
            ffma2(acc[i][1], aa, b23);
        }
    }
#pragma unroll
    for (int i = 0; i < 4; i++) {
        int v = v0 + m0 + i;
        if (v < V) {
            float4 o;
            upk2(acc[i][0], o.x, o.y);
            upk2(acc[i][1], o.z, o.w);
            *(float4*)&outP[(size_t)v * NGATE + j0 + n0] = o;
        }
    }
}

// ---------------- Stage A2: fold numerical path + bias; transpose Whh ---------
__global__ __launch_bounds__(128) void kernelA2(
    const float* __restrict__ Wih, const float* __restrict__ num_W,
    const float* __restrict__ num_b, const float* __restrict__ bih,
    const float* __restrict__ bhh, const float* __restrict__ Whh)
{
    const int j = blockIdx.x, tid = threadIdx.x;
    __shared__ float wrow[128];
    wrow[tid] = Wih[(size_t)j * INDIM + 7680 + tid];
    g_WhhT[tid * NGATE + j] = Whh[j * LHID + tid];
    __syncthreads();
    if (tid < 84) {
        float s = 0.f;
        for (int k = 0; k < 128; k++) s += wrow[k] * num_W[k * 84 + tid];
        g_WcombT[tid * NGATE + j] = s;
    } else if (tid == 84) {
        float s = bih[j] + bhh[j];
        for (int k = 0; k < 128; k++) s += num_b[k] * wrow[k];
        g_bias[j] = s;
    }
}

// ---------------- Stage B: gather-sum gates + LSTM cell (8 rows/block) --------
__global__ __launch_bounds__(128) void kernelB(
    const int* __restrict__ ab_ids, const int* __restrict__ mv_ids,
    const float* __restrict__ numerical, const float* __restrict__ h0,
    const float* __restrict__ c0,
    float* __restrict__ h1_dup, float* __restrict__ c1_dup, int dup)
{
    __shared__ float num_s[8][84];
    __shared__ float h0_s[8][128];
    __shared__ int   ids_s[8][64];
    __shared__ float gs[8][512];
    const int tid = threadIdx.x;
    const int b0 = blockIdx.x * 8;

    for (int idx = tid; idx < 8 * 84; idx += 128)  num_s[idx / 84][idx % 84] = numerical[b0 * 84 + idx];
    for (int idx = tid; idx < 8 * 128; idx += 128) h0_s[idx >> 7][idx & 127] = h0[b0 * 128 + idx];
    for (int idx = tid; idx < 8 * 12; idx += 128)  ids_s[idx / 12][idx % 12] = ab_ids[b0 * 12 + idx];
    for (int idx = tid; idx < 8 * 48; idx += 128)  ids_s[idx / 48][12 + idx % 48] = mv_ids[b0 * 48 + idx];
    __syncthreads();

    u64 acc[8][2];
    {
        const float4 bb = *(const float4*)&g_bias[tid * 4];
        u64 b01 = pk2(bb.x, bb.y), b23 = pk2(bb.z, bb.w);
#pragma unroll
        for (int r = 0; r < 8; r++) { acc[r][0] = b01; acc[r][1] = b23; }
    }

    for (int s = 0; s < 12; s++) {
#pragma unroll
        for (int r = 0; r < 8; r++) {
            const ulonglong2 v = *(const ulonglong2*)(g_Tab +
                ((size_t)(s * NAB + ids_s[r][s]) << 9) + (tid << 2));
            fadd2(acc[r][0], v.x); fadd2(acc[r][1], v.y);
        }
    }
    for (int s = 0; s < 48; s++) {
#pragma unroll
        for (int r = 0; r < 8; r++) {
            const ulonglong2 v = *(const ulonglong2*)(g_Tmv +
                ((size_t)(s * NMV + ids_s[r][12 + s]) << 9) + (tid << 2));
            fadd2(acc[r][0], v.x); fadd2(acc[r][1], v.y);
        }
    }
    for (int t = 0; t < 84; t++) {
        const ulonglong2 w = *(const ulonglong2*)(g_WcombT + t * NGATE + (tid << 2));
#pragma unroll
        for (int r = 0; r < 8; r++) {
            float nv = num_s[r][t];
            u64 aa = pk2(nv, nv);
            ffma2(acc[r][0], aa, w.x); ffma2(acc[r][1], aa, w.y);
        }
    }
    for (int k = 0; k < 128; k++) {
        const ulonglong2 w = *(const ulonglong2*)(g_WhhT + k * NGATE + (tid << 2));
#pragma unroll
        for (int r = 0; r < 8; r++) {
            float hv = h0_s[r][k];
            u64 aa = pk2(hv, hv);
            ffma2(acc[r][0], aa, w.x); ffma2(acc[r][1], aa, w.y);
        }
    }
#pragma unroll
    for (int r = 0; r < 8; r++) {
        float x0, x1, x2, x3;
        upk2(acc[r][0], x0, x1); upk2(acc[r][1], x2, x3);
        *(float4*)&gs[r][tid * 4] = make_float4(x0, x1, x2, x3);
    }
    __syncthreads();

    const int h = tid;
#pragma unroll
    for (int r = 0; r < 8; r++) {
        float iv = gs[r][h], fv = gs[r][128 + h], gv = gs[r][256 + h], ov = gs[r][384 + h];
        iv = 1.f / (1.f + expf(-iv));
        fv = 1.f / (1.f + expf(-fv));
        ov = 1.f / (1.f + expf(-ov));
        gv = tanhf(gv);
        float c0v = c0[(b0 + r) * LHID + h];
        float c1v = fv * c0v + iv * gv;
        float h1v = ov * tanhf(c1v);
        g_c1[(b0 + r) * LHID + h] = c1v;
        g_h1[(b0 + r) * LHID + h] = h1v;
        if (dup) {
            c1_dup[(b0 + r) * LHID + h] = c1v;
            h1_dup[(b0 + r) * LHID + h] = h1v;
        }
    }
}

// ---------------- Stage C: MLP head + masked softmax (16 rows/block) ----------
__global__ __launch_bounds__(128) void kernelC(
    const float* __restrict__ W1, const float* __restrict__ b1,
    const float* __restrict__ W2, const float* __restrict__ b2,
    const float* __restrict__ Wa, const float* __restrict__ ba,
    const float* __restrict__ mask, float* __restrict__ outp)
{
    extern __shared__ float sm[];
    float* W1s = sm;                    // 64*128
    float* W2s = W1s + 8192;            // 128*64
    float* Was = W2s + 8192;            // 9*132
    float* b1s = Was + 1188;            // 64
    float* b2s = b1s + 64;              // 128
    float* bas = b2s + 128;             // 16
    float* h1s = bas + 16;              // 16*129
    float* t1s = h1s + 16 * 129;        // 16*65
    float* fts = t1s + 16 * 65;         // 16*129
    float* lgs = fts + 16 * 129;        // 16*12
    const int tid = threadIdx.x;
    const int b0 = blockIdx.x * 16;

    for (int i = tid; i < 8192; i += 128) W1s[i] = W1[i];
    for (int i = tid; i < 8192; i += 128) W2s[i] = W2[i];
    for (int i = tid; i < 9 * 128; i += 128) Was[(i >> 7) * 132 + (i & 127)] = Wa[i];
    if (tid < 64) b1s[tid] = b1[tid];
    b2s[tid] = b2[tid];
    if (tid < 9) bas[tid] = ba[tid];
    for (int i = tid; i < 16 * 128; i += 128) h1s[(i >> 7) * 129 + (i & 127)] = g_h1[b0 * 128 + i];
    __syncthreads();

    const int r = tid & 15, gq = tid >> 4;  // gq in 0..7
#pragma unroll
    for (int jt = 0; jt < 8; jt++) {
        int j = jt * 8 + gq;
        float s = b1s[j];
        for (int k = 0; k < 128; k++) s += h1s[r * 129 + k] * W1s[j * 128 + k];
        t1s[r * 65 + j] = fmaxf(s, 0.f);
    }
    __syncthreads();
#pragma unroll
    for (int kt = 0; kt < 16; kt++) {
        int kk = kt * 8 + gq;
        float s = b2s[kk];
        for (int j = 0; j < 64; j++) s += t1s[r * 65 + j] * W2s[kk * 64 + j];
        fts[r * 129 + kk] = s;
    }
    __syncthreads();
    for (int idx = tid; idx < 144; idx += 128) {
        int rr = idx / 9, a = idx % 9;
        float s = bas[a];
        for (int k = 0; k < 128; k++) s += fts[rr * 129 + k] * Was[a * 132 + k];
        lgs[rr * 12 + a] = s;
    }
    __syncthreads();
    if (tid < 16) {
        int b = b0 + tid;
        float mx = -1e30f;
        for (int a = 0; a < 9; a++) mx = fmaxf(mx, lgs[tid * 12 + a]);
        float e[9]; float se = 0.f;
        for (int a = 0; a < 9; a++) { e[a] = expf(lgs[tid * 12 + a] - mx); se += e[a]; }
        float pm[9]; float ms = 0.f;
        for (int a = 0; a < 9; a++) {
            float p = e[a] / se;
            pm[a] = p * mask[b * 9 + a];
            ms += pm[a];
        }
        for (int a = 0; a < 9; a++)
            outp[b * 9 + a] = (ms > 0.f) ? pm[a] / ms : e[a] / se;
    }
}

// ---------------- host ---------------------------------------------------------
extern "C" void kernel_launch(void* const* d_in, const int* in_sizes, int n_in,
                              void* d_out, int out_size)
{
    const int*   ab_ids    = (const int*)d_in[0];
    const int*   mv_ids    = (const int*)d_in[1];
    const float* numerical = (const float*)d_in[2];
    const float* mask      = (const float*)d_in[3];
    const float* h0        = (const float*)d_in[4];
    const float* c0        = (const float*)d_in[5];
    const float* ability_emb = (const float*)d_in[6];
    const float* move_emb  = (const float*)d_in[7];
    const float* num_W     = (const float*)d_in[8];
    const float* num_b     = (const float*)d_in[9];
    const float* Wih       = (const float*)d_in[10];
    const float* Whh       = (const float*)d_in[11];
    const float* bih       = (const float*)d_in[12];
    const float* bhh       = (const float*)d_in[13];
    const float* W1        = (const float*)d_in[14];
    const float* b1        = (const float*)d_in[15];
    const float* W2        = (const float*)d_in[16];
    const float* b2        = (const float*)d_in[17];
    const float* Wa        = (const float*)d_in[18];
    const float* ba        = (const float*)d_in[19];
    float* outp = (float*)d_out;

    float *tab = nullptr, *tmv = nullptr;
    cudaGetSymbolAddress((void**)&tab, g_Tab);
    cudaGetSymbolAddress((void**)&tmv, g_Tmv);

    const int smA = (64 * 128 * 2 + 128 * SBPAD) * 4;   // 100352 B
    const int smC = 23140 * 4;                           // 92560 B
    cudaFuncSetAttribute(kernelA, cudaFuncAttributeMaxDynamicSharedMemorySize, smA);
    cudaFuncSetAttribute(kernelC, cudaFuncAttributeMaxDynamicSharedMemorySize, smC);

    const int full = (out_size >= BNUM * (9 + LHID + LHID));
    float* h1d = full ? (outp + BNUM * 9) : nullptr;
    float* c1d = full ? (outp + BNUM * 9 + BNUM * LHID) : nullptr;

    dim3 gAab(5, 8, 12);    // ceil(300/64) x (512/64) x 12 slots
    dim3 gAmv(15, 8, 48);   // ceil(900/64) x (512/64) x 48 slots
    kernelA<<<gAab, 256, smA>>>(ability_emb, NAB, Wih, 0, tab);
    kernelA<<<gAmv, 256, smA>>>(move_emb, NMV, Wih, 12 * EDIM, tmv);
    kernelA2<<<NGATE, 128>>>(Wih, num_W, num_b, bih, bhh, Whh);
    kernelB<<<BNUM / 8, 128>>>(ab_ids, mv_ids, numerical, h0, c0, h1d, c1d, full);
    kernelC<<<BNUM / 16, 128, smC>>>(W1, b1, W2, b2, Wa, ba, mask, outp);
}

// round 3
// speedup vs baseline: 1.8859x; 1.8859x over previous
#include <cuda_runtime.h>
#include <cuda_bf16.h>
#include <math.h>
#include <cstdint>

#define BNUM 4096
#define EDIM 128
#define LHID 128
#define HDIM 64
#define NGATE 512
#define NAB 300
#define NMV 900
#define INDIM 7808

#define NCOL_MV (48 * NGATE)   // 24576
#define NCOL_AB (12 * NGATE)   // 6144
#define MPAD_MV 1024
#define MPAD_AB 384

// ---------------- scratch (device globals; no allocation allowed) -------------
__device__ float g_Tab[NAB * NCOL_AB];        // [v][12][512]  7.4 MB
__device__ float g_Tmv[NMV * NCOL_MV];        // [v][48][512]  88.5 MB
__device__ __nv_bfloat16 g_Amv[MPAD_MV * 384];
__device__ __nv_bfloat16 g_Aab[MPAD_AB * 384];
__device__ __nv_bfloat16 g_Bmv[NCOL_MV * 384];   // 18.9 MB
__device__ __nv_bfloat16 g_Bab[NCOL_AB * 384];   // 4.7 MB
__device__ float g_WcombT[84 * NGATE];
__device__ float g_WhhT[LHID * NGATE];
__device__ float g_bias[NGATE];
__device__ float g_h1[BNUM * LHID];
__device__ float g_c1[BNUM * LHID];

typedef unsigned long long u64;

__device__ __forceinline__ u64 pk2(float x, float y) {
    u64 r;
    asm("mov.b64 %0, {%1, %2};" : "=l"(r) : "r"(__float_as_uint(x)), "r"(__float_as_uint(y)));
    return r;
}
__device__ __forceinline__ void upk2(u64 v, float& x, float& y) {
    unsigned a, b;
    asm("mov.b64 {%0, %1}, %2;" : "=r"(a), "=r"(b) : "l"(v));
    x = __uint_as_float(a); y = __uint_as_float(b);
}
__device__ __forceinline__ void ffma2(u64& d, u64 a, u64 b) {
    asm("fma.rn.f32x2 %0, %1, %2, %0;" : "+l"(d) : "l"(a), "l"(b));
}
__device__ __forceinline__ void fadd2(u64& d, u64 a) {
    asm("add.rn.f32x2 %0, %1, %0;" : "+l"(d) : "l"(a));
}

__device__ __forceinline__ uint32_t smem_to_u32(const void* p) {
    uint32_t a;
    asm("{ .reg .u64 t; cvta.to.shared.u64 t, %1; cvt.u32.u64 %0, t; }" : "=r"(a) : "l"(p));
    return a;
}

__device__ __forceinline__ void ldsm4(uint32_t* r, uint32_t addr) {
    asm volatile("ldmatrix.sync.aligned.m8n8.x4.shared.b16 {%0,%1,%2,%3}, [%4];"
        : "=r"(r[0]), "=r"(r[1]), "=r"(r[2]), "=r"(r[3]) : "r"(addr));
}
__device__ __forceinline__ void mma16816(float* c, const uint32_t* a, uint32_t b0, uint32_t b1) {
    asm volatile("mma.sync.aligned.m16n8k16.row.col.f32.bf16.bf16.f32 "
        "{%0,%1,%2,%3}, {%4,%5,%6,%7}, {%8,%9}, {%0,%1,%2,%3};"
        : "+f"(c[0]), "+f"(c[1]), "+f"(c[2]), "+f"(c[3])
        : "r"(a[0]), "r"(a[1]), "r"(a[2]), "r"(a[3]), "r"(b0), "r"(b1));
}

// ---------------- split kernels (fp32 -> [hi|lo|hi] / [hi|hi|lo] bf16) --------
__global__ __launch_bounds__(128) void kernelSplitA(
    const float* __restrict__ emb, int V, __nv_bfloat16* __restrict__ out)
{
    int v = blockIdx.x, k = threadIdx.x;
    float x = (v < V) ? emb[v * EDIM + k] : 0.f;
    __nv_bfloat16 hi = __float2bfloat16(x);
    __nv_bfloat16 lo = __float2bfloat16(x - __bfloat162float(hi));
    out[v * 384 + k] = hi;
    out[v * 384 + 128 + k] = lo;
    out[v * 384 + 256 + k] = hi;
}

__global__ __launch_bounds__(128) void kernelSplitB(
    const float* __restrict__ Wih, int colBase, __nv_bfloat16* __restrict__ out)
{
    int n = blockIdx.x, k = threadIdx.x;
    int s = n >> 9, j = n & 511;
    float x = Wih[(size_t)j * INDIM + colBase + s * EDIM + k];
    __nv_bfloat16 hi = __float2bfloat16(x);
    __nv_bfloat16 lo = __float2bfloat16(x - __bfloat162float(hi));
    out[n * 384 + k] = hi;
    out[n * 384 + 128 + k] = hi;
    out[n * 384 + 256 + k] = lo;
}

// ---------------- Stage A: HMMA GEMM  C[M,N] = A[M,384] @ B[N,384]^T ----------
// smem tile: 128 rows x 32 bf16 (64B/row), chunk = 16B unit, swizzled.
__device__ __forceinline__ uint32_t swz(int row, int chunk) {
    return (uint32_t)(row * 64 + ((chunk ^ ((row >> 1) & 3)) * 16));
}

__global__ __launch_bounds__(256, 2) void kernelTC(
    const __nv_bfloat16* __restrict__ A, const __nv_bfloat16* __restrict__ B,
    float* __restrict__ C, int Mrows, int Ncols)
{
    __shared__ __align__(16) char As[2][8192];
    __shared__ __align__(16) char Bs[2][8192];

    const int tid = threadIdx.x;
    const int warp = tid >> 5, lane = tid & 31;
    const int warp_m = warp >> 2;          // 0..1  -> 64 rows each
    const int warp_n = warp & 3;           // 0..3  -> 32 cols each
    const int mrow0 = blockIdx.y * 128;
    const int nrow0 = blockIdx.x * 128;

    const uint32_t asBase = smem_to_u32(As);
    const uint32_t bsBase = smem_to_u32(Bs);

    const int r0 = tid >> 2;               // 0..63 (t=0), +64 (t=1)
    const int ch0 = tid & 3;

    float acc[4][4][4];
#pragma unroll
    for (int i = 0; i < 4; i++)
#pragma unroll
        for (int j = 0; j < 4; j++)
#pragma unroll
            for (int q = 0; q < 4; q++) acc[i][j][q] = 0.f;

    // prologue: load chunk 0 into buf 0
    {
#pragma unroll
        for (int t = 0; t < 2; t++) {
            int r = r0 + t * 64;
            uint4 va = *(const uint4*)(A + (size_t)(mrow0 + r) * 384 + ch0 * 8);
            uint4 vb = *(const uint4*)(B + (size_t)(nrow0 + r) * 384 + ch0 * 8);
            *(uint4*)(As[0] + swz(r, ch0)) = va;
            *(uint4*)(Bs[0] + swz(r, ch0)) = vb;
        }
    }
    __syncthreads();

    const int lrow = lane & 15;            // row within 16-row ldmatrix group
    const int lsel = lane >> 4;            // chunk select 0/1

#pragma unroll
    for (int c = 0; c < 12; c++) {
        uint4 pa[2], pb[2];
        if (c < 11) {
#pragma unroll
            for (int t = 0; t < 2; t++) {
                int r = r0 + t * 64;
                pa[t] = *(const uint4*)(A + (size_t)(mrow0 + r) * 384 + (c + 1) * 32 + ch0 * 8);
                pb[t] = *(const uint4*)(B + (size_t)(nrow0 + r) * 384 + (c + 1) * 32 + ch0 * 8);
            }
        }
        const uint32_t ab = asBase + (c & 1) * 8192;
        const uint32_t bb = bsBase + (c & 1) * 8192;
#pragma unroll
        for (int ks = 0; ks < 2; ks++) {
            uint32_t af[4][4], bf[2][4];
#pragma unroll
            for (int mt = 0; mt < 4; mt++)
                ldsm4(af[mt], ab + swz(warp_m * 64 + mt * 16 + lrow, ks * 2 + lsel));
#pragma unroll
            for (int pr = 0; pr < 2; pr++)
                ldsm4(bf[pr], bb + swz(warp_n * 32 + pr * 16 + lrow, ks * 2 + lsel));
#pragma unroll
            for (int mt = 0; mt < 4; mt++)
#pragma unroll
                for (int nt = 0; nt < 4; nt++) {
                    int pr = nt >> 1, hf = nt & 1;
                    mma16816(acc[mt][nt], af[mt], bf[pr][hf], bf[pr][2 + hf]);
                }
        }
        if (c < 11) {
            int nb = (c + 1) & 1;
#pragma unroll
            for (int t = 0; t < 2; t++) {
                int r = r0 + t * 64;
                *(uint4*)(As[nb] + swz(r, ch0)) = pa[t];
                *(uint4*)(Bs[nb] + swz(r, ch0)) = pb[t];
            }
            __syncthreads();
        }
    }

    // epilogue: c frag layout -> rows (lane/4, +8), cols (lane%4)*2
    const int erow = lane >> 2, ecol = (lane & 3) * 2;
#pragma unroll
    for (int mt = 0; mt < 4; mt++) {
#pragma unroll
        for (int nt = 0; nt < 4; nt++) {
            int mg = mrow0 + warp_m * 64 + mt * 16 + erow;
            int cg = nrow0 + warp_n * 32 + nt * 8 + ecol;
            if (mg < Mrows)
                *(float2*)(C + (size_t)mg * Ncols + cg) = make_float2(acc[mt][nt][0], acc[mt][nt][1]);
            if (mg + 8 < Mrows)
                *(float2*)(C + (size_t)(mg + 8) * Ncols + cg) = make_float2(acc[mt][nt][2], acc[mt][nt][3]);
        }
    }
}

// ---------------- Stage A2: fold numerical path + bias; transpose Whh ---------
__global__ __launch_bounds__(128) void kernelA2(
    const float* __restrict__ Wih, const float* __restrict__ num_W,
    const float* __restrict__ num_b, const float* __restrict__ bih,
    const float* __restrict__ bhh, const float* __restrict__ Whh)
{
    const int j = blockIdx.x, tid = threadIdx.x;
    __shared__ float wrow[128];
    wrow[tid] = Wih[(size_t)j * INDIM + 7680 + tid];
    g_WhhT[tid * NGATE + j] = Whh[j * LHID + tid];
    __syncthreads();
    if (tid < 84) {
        float s = 0.f;
        for (int k = 0; k < 128; k++) s += wrow[k] * num_W[k * 84 + tid];
        g_WcombT[tid * NGATE + j] = s;
    } else if (tid == 84) {
        float s = bih[j] + bhh[j];
        for (int k = 0; k < 128; k++) s += num_b[k] * wrow[k];
        g_bias[j] = s;
    }
}

// ---------------- Stage B: gather-sum gates + LSTM cell (8 rows, 256 thr) -----
__global__ __launch_bounds__(256) void kernelB(
    const int* __restrict__ ab_ids, const int* __restrict__ mv_ids,
    const float* __restrict__ numerical, const float* __restrict__ h0,
    const float* __restrict__ c0,
    float* __restrict__ h1_dup, float* __restrict__ c1_dup, int dup)
{
    __shared__ float num_s[8][84];
    __shared__ float h0_s[8][128];
    __shared__ int   ids_s[8][64];
    __shared__ float gs[8][512];
    const int tid = threadIdx.x;
    const int b0 = blockIdx.x * 8;

    for (int idx = tid; idx < 8 * 84; idx += 256)  num_s[idx / 84][idx % 84] = numerical[b0 * 84 + idx];
    for (int idx = tid; idx < 8 * 128; idx += 256) h0_s[idx >> 7][idx & 127] = h0[b0 * 128 + idx];
    for (int idx = tid; idx < 8 * 12; idx += 256)  ids_s[idx / 12][idx % 12] = ab_ids[b0 * 12 + idx];
    for (int idx = tid; idx < 8 * 48; idx += 256)  ids_s[idx / 48][12 + idx % 48] = mv_ids[b0 * 48 + idx];
    __syncthreads();

    u64 acc[8];
    {
        const u64 bb = *(const u64*)&g_bias[tid * 2];
#pragma unroll
        for (int r = 0; r < 8; r++) acc[r] = bb;
    }

    for (int s = 0; s < 12; s++) {
#pragma unroll
        for (int r = 0; r < 8; r++) {
            const u64 v = *(const u64*)(g_Tab + ((size_t)(ids_s[r][s] * 12 + s) << 9) + tid * 2);
            fadd2(acc[r], v);
        }
    }
    for (int s = 0; s < 48; s++) {
#pragma unroll
        for (int r = 0; r < 8; r++) {
            const u64 v = *(const u64*)(g_Tmv + ((size_t)(ids_s[r][12 + s] * 48 + s) << 9) + tid * 2);
            fadd2(acc[r], v);
        }
    }
    for (int t = 0; t < 84; t++) {
        const u64 w = *(const u64*)(g_WcombT + t * NGATE + tid * 2);
#pragma unroll
        for (int r = 0; r < 8; r++) {
            float nv = num_s[r][t];
            ffma2(acc[r], pk2(nv, nv), w);
        }
    }
    for (int k = 0; k < 128; k++) {
        const u64 w = *(const u64*)(g_WhhT + k * NGATE + tid * 2);
#pragma unroll
        for (int r = 0; r < 8; r++) {
            float hv = h0_s[r][k];
            ffma2(acc[r], pk2(hv, hv), w);
        }
    }
#pragma unroll
    for (int r = 0; r < 8; r++) {
        float x0, x1;
        upk2(acc[r], x0, x1);
        *(float2*)&gs[r][tid * 2] = make_float2(x0, x1);
    }
    __syncthreads();

    const int h = tid & 127;
#pragma unroll
    for (int rr = 0; rr < 4; rr++) {
        int r = (tid >> 7) + rr * 2;
        float iv = gs[r][h], fv = gs[r][128 + h], gv = gs[r][256 + h], ov = gs[r][384 + h];
        iv = 1.f / (1.f + expf(-iv));
        fv = 1.f / (1.f + expf(-fv));
        ov = 1.f / (1.f + expf(-ov));
        gv = tanhf(gv);
        float c0v = c0[(b0 + r) * LHID + h];
        float c1v = fv * c0v + iv * gv;
        float h1v = ov * tanhf(c1v);
        g_c1[(b0 + r) * LHID + h] = c1v;
        g_h1[(b0 + r) * LHID + h] = h1v;
        if (dup) {
            c1_dup[(b0 + r) * LHID + h] = c1v;
            h1_dup[(b0 + r) * LHID + h] = h1v;
        }
    }
}

// ---------------- Stage C: MLP head + masked softmax (16 rows/block) ----------
__global__ __launch_bounds__(128) void kernelC(
    const float* __restrict__ W1, const float* __restrict__ b1,
    const float* __restrict__ W2, const float* __restrict__ b2,
    const float* __restrict__ Wa, const float* __restrict__ ba,
    const float* __restrict__ mask, float* __restrict__ outp)
{
    extern __shared__ float sm[];
    float* W1s = sm;
    float* W2s = W1s + 8192;
    float* Was = W2s + 8192;
    float* b1s = Was + 1188;
    float* b2s = b1s + 64;
    float* bas = b2s + 128;
    float* h1s = bas + 16;
    float* t1s = h1s + 16 * 129;
    float* fts = t1s + 16 * 65;
    float* lgs = fts + 16 * 129;
    const int tid = threadIdx.x;
    const int b0 = blockIdx.x * 16;

    for (int i = tid; i < 8192; i += 128) W1s[i] = W1[i];
    for (int i = tid; i < 8192; i += 128) W2s[i] = W2[i];
    for (int i = tid; i < 9 * 128; i += 128) Was[(i >> 7) * 132 + (i & 127)] = Wa[i];
    if (tid < 64) b1s[tid] = b1[tid];
    b2s[tid] = b2[tid];
    if (tid < 9) bas[tid] = ba[tid];
    for (int i = tid; i < 16 * 128; i += 128) h1s[(i >> 7) * 129 + (i & 127)] = g_h1[b0 * 128 + i];
    __syncthreads();

    const int r = tid & 15, gq = tid >> 4;
#pragma unroll
    for (int jt = 0; jt < 8; jt++) {
        int j = jt * 8 + gq;
        float s = b1s[j];
        for (int k = 0; k < 128; k++) s += h1s[r * 129 + k] * W1s[j * 128 + k];
        t1s[r * 65 + j] = fmaxf(s, 0.f);
    }
    __syncthreads();
#pragma unroll
    for (int kt = 0; kt < 16; kt++) {
        int kk = kt * 8 + gq;
        float s = b2s[kk];
        for (int j = 0; j < 64; j++) s += t1s[r * 65 + j] * W2s[kk * 64 + j];
        fts[r * 129 + kk] = s;
    }
    __syncthreads();
    for (int idx = tid; idx < 144; idx += 128) {
        int rr = idx / 9, a = idx % 9;
        float s = bas[a];
        for (int k = 0; k < 128; k++) s += fts[rr * 129 + k] * Was[a * 132 + k];
        lgs[rr * 12 + a] = s;
    }
    __syncthreads();
    if (tid < 16) {
        int b = b0 + tid;
        float mx = -1e30f;
        for (int a = 0; a < 9; a++) mx = fmaxf(mx, lgs[tid * 12 + a]);
        float e[9]; float se = 0.f;
        for (int a = 0; a < 9; a++) { e[a] = expf(lgs[tid * 12 + a] - mx); se += e[a]; }
        float pm[9]; float ms = 0.f;
        for (int a = 0; a < 9; a++) {
            float p = e[a] / se;
            pm[a] = p * mask[b * 9 + a];
            ms += pm[a];
        }
        for (int a = 0; a < 9; a++)
            outp[b * 9 + a] = (ms > 0.f) ? pm[a] / ms : e[a] / se;
    }
}

// ---------------- host ---------------------------------------------------------
extern "C" void kernel_launch(void* const* d_in, const int* in_sizes, int n_in,
                              void* d_out, int out_size)
{
    const int*   ab_ids    = (const int*)d_in[0];
    const int*   mv_ids    = (const int*)d_in[1];
    const float* numerical = (const float*)d_in[2];
    const float* mask      = (const float*)d_in[3];
    const float* h0        = (const float*)d_in[4];
    const float* c0        = (const float*)d_in[5];
    const float* ability_emb = (const float*)d_in[6];
    const float* move_emb  = (const float*)d_in[7];
    const float* num_W     = (const float*)d_in[8];
    const float* num_b     = (const float*)d_in[9];
    const float* Wih       = (const float*)d_in[10];
    const float* Whh       = (const float*)d_in[11];
    const float* bih       = (const float*)d_in[12];
    const float* bhh       = (const float*)d_in[13];
    const float* W1        = (const float*)d_in[14];
    const float* b1        = (const float*)d_in[15];
    const float* W2        = (const float*)d_in[16];
    const float* b2        = (const float*)d_in[17];
    const float* Wa        = (const float*)d_in[18];
    const float* ba        = (const float*)d_in[19];
    float* outp = (float*)d_out;

    float *tab = nullptr, *tmv = nullptr;
    __nv_bfloat16 *amv = nullptr, *aab = nullptr, *bmv = nullptr, *bab = nullptr;
    cudaGetSymbolAddress((void**)&tab, g_Tab);
    cudaGetSymbolAddress((void**)&tmv, g_Tmv);
    cudaGetSymbolAddress((void**)&amv, g_Amv);
    cudaGetSymbolAddress((void**)&aab, g_Aab);
    cudaGetSymbolAddress((void**)&bmv, g_Bmv);
    cudaGetSymbolAddress((void**)&bab, g_Bab);

    const int smC = 23140 * 4;
    cudaFuncSetAttribute(kernelC, cudaFuncAttributeMaxDynamicSharedMemorySize, smC);

    const int full = (out_size >= BNUM * (9 + LHID + LHID));
    float* h1d = full ? (outp + BNUM * 9) : nullptr;
    float* c1d = full ? (outp + BNUM * 9 + BNUM * LHID) : nullptr;

    // Stage A prep: bf16 split operands
    kernelSplitA<<<MPAD_MV, 128>>>(move_emb, NMV, amv);
    kernelSplitA<<<MPAD_AB, 128>>>(ability_emb, NAB, aab);
    kernelSplitB<<<NCOL_MV, 128>>>(Wih, 12 * EDIM, bmv);
    kernelSplitB<<<NCOL_AB, 128>>>(Wih, 0, bab);
    kernelA2<<<NGATE, 128>>>(Wih, num_W, num_b, bih, bhh, Whh);

    // Stage A: HMMA table GEMMs
    dim3 gMV(NCOL_MV / 128, MPAD_MV / 128);   // (192, 8)
    dim3 gAB(NCOL_AB / 128, MPAD_AB / 128);   // (48, 3)
    kernelTC<<<gMV, 256>>>(amv, bmv, tmv, NMV, NCOL_MV);
    kernelTC<<<gAB, 256>>>(aab, bab, tab, NAB, NCOL_AB);

    kernelB<<<BNUM / 8, 256>>>(ab_ids, mv_ids, numerical, h0, c0, h1d, c1d, full);
    kernelC<<<BNUM / 16, 128, smC>>>(W1, b1, W2, b2, Wa, ba, mask, outp);
}